// round 15
// baseline (speedup 1.0000x reference)
#include <cuda_runtime.h>
#include <cuda_bf16.h>
#include <cstdint>

#define N_NODES  200000
#define N_EDGES  1600000
#define N_GRAPHS 10000
#define IN_F     74
#define HID      128

#define SCAN_B   1024
#define N_SCANB  ((N_NODES + SCAN_B - 1) / SCAN_B)   // 196
#define NSM      152
#define NTILES   ((N_NODES + 127) / 128)             // 1563

// interleaved split rows: h/agg = 256 bf16 [hi128|lo128] = 512B; x = 160 bf16 [hi80|lo80] = 320B
__device__ __align__(16) __nv_bfloat16 g_h  [(size_t)N_NODES * 256];
__device__ __align__(16) __nv_bfloat16 g_agg[(size_t)N_NODES * 256];
__device__ __align__(16) __nv_bfloat16 g_xs [(size_t)N_NODES * 160];
__device__ __align__(16) __nv_bfloat16 g_w  [4 * HID * 256];     // [l][n][hi128|lo128], W^T
__device__ __align__(16) __nv_bfloat16 g_win[HID * 160];         // w_in^T [n][hi80|lo80]
__device__ __align__(16) int   g_deg_out[N_NODES];
__device__ __align__(16) int   g_deg_in [N_NODES];
__device__ __align__(16) float g_norm_src[N_NODES];
__device__ __align__(16) float g_norm_dst[N_NODES];
__device__ __align__(16) float g_pooled[(size_t)N_GRAPHS * HID];
__device__ __align__(16) int   g_row_ptr[N_NODES + 1];
__device__ __align__(16) int   g_cursor [N_NODES];
__device__ __align__(16) int   g_csr_src[N_EDGES];
__device__ __align__(16) int   g_bsums  [N_SCANB];

__device__ __forceinline__ float fast_silu(float w) {
    float t, r;
    asm("ex2.approx.f32 %0, %1;" : "=f"(t) : "f"(-1.4426950408889634f * w));
    asm("rcp.approx.f32 %0, %1;" : "=f"(r) : "f"(1.f + t));
    return w * r;
}

__device__ __forceinline__ uint32_t smem_u32(const void* p) {
    uint32_t a;
    asm("{ .reg .u64 t; cvta.to.shared.u64 t, %1; cvt.u32.u64 %0, t; }" : "=r"(a) : "l"(p));
    return a;
}

__device__ __forceinline__ void mbar_wait(uint32_t mb, uint32_t parity) {
    asm volatile("{\n\t.reg .pred P1;\n\t"
                 "WL_%=:\n\t"
                 "mbarrier.try_wait.parity.acquire.cta.shared::cta.b64 P1, [%0], %1, 0x989680;\n\t"
                 "@P1 bra.uni WD_%=;\n\t"
                 "bra.uni WL_%=;\n\t"
                 "WD_%=:\n\t}" :: "r"(mb), "r"(parity) : "memory");
}

#define LDSM4(r, addr)                                                          \
    asm volatile("ldmatrix.sync.aligned.m8n8.x4.shared.b16 {%0,%1,%2,%3}, [%4];" \
                 : "=r"((r)[0]), "=r"((r)[1]), "=r"((r)[2]), "=r"((r)[3])        \
                 : "r"(addr))

#define MMA16816(c, a, b)                                                        \
    asm volatile("mma.sync.aligned.m16n8k16.row.col.f32.bf16.bf16.f32 "          \
                 "{%0,%1,%2,%3}, {%4,%5,%6,%7}, {%8,%9}, {%0,%1,%2,%3};"         \
                 : "+f"((c)[0]), "+f"((c)[1]), "+f"((c)[2]), "+f"((c)[3])        \
                 : "r"((a)[0]), "r"((a)[1]), "r"((a)[2]), "r"((a)[3]),           \
                   "r"((b)[0]), "r"((b)[1]))

__device__ __forceinline__ void split_store2(float va, float vb, __nv_bfloat16* hi_p,
                                             __nv_bfloat16* lo_p) {
    __nv_bfloat16 ha = __float2bfloat16(va);
    __nv_bfloat16 hb = __float2bfloat16(vb);
    *reinterpret_cast<uint32_t*>(hi_p) =
        (uint32_t)__bfloat16_as_ushort(ha) | ((uint32_t)__bfloat16_as_ushort(hb) << 16);
    *reinterpret_cast<uint32_t*>(lo_p) =
        (uint32_t)__bfloat16_as_ushort(__float2bfloat16(va - __bfloat162float(ha)))
      | ((uint32_t)__bfloat16_as_ushort(__float2bfloat16(vb - __bfloat162float(hb))) << 16);
}

// ---------------- fused prep: zeros + weight split/transpose + x split -----------------
__global__ __launch_bounds__(256) void prepx_kernel(const float* __restrict__ gw,
                                                    const float* __restrict__ w_out,
                                                    const float* __restrict__ w_in,
                                                    const float* __restrict__ x) {
    int i = blockIdx.x * blockDim.x + threadIdx.x;
    if (i < N_NODES / 4) {
        reinterpret_cast<int4*>(g_deg_out)[i] = make_int4(0, 0, 0, 0);
        reinterpret_cast<int4*>(g_deg_in )[i] = make_int4(0, 0, 0, 0);
    }
    if (i < N_GRAPHS * HID / 4)
        reinterpret_cast<float4*>(g_pooled)[i] = make_float4(0.f, 0.f, 0.f, 0.f);
    if (i < 4 * HID * HID) {
        int l = i >> 14, n = (i >> 7) & 127, k = i & 127;
        float v = (l < 3) ? gw[l * HID * HID + k * HID + n] : w_out[k * HID + n];
        __nv_bfloat16 hb = __float2bfloat16(v);
        size_t base = ((size_t)(l * 128 + n)) * 256;
        g_w[base + k]       = hb;
        g_w[base + 128 + k] = __float2bfloat16(v - __bfloat162float(hb));
    }
    if (i < HID * 80) {
        int n = i / 80, k = i % 80;
        float v = (k < IN_F) ? w_in[k * HID + n] : 0.f;
        __nv_bfloat16 hb = __float2bfloat16(v);
        g_win[n * 160 + k]      = hb;
        g_win[n * 160 + 80 + k] = __float2bfloat16(v - __bfloat162float(hb));
    }
    // x split: one warp per row
    int row  = i >> 5;
    int lane = i & 31;
    if (row < N_NODES) {
        const float* xr = x + (size_t)row * IN_F;
        __nv_bfloat16* o = g_xs + (size_t)row * 160;
#pragma unroll
        for (int c = lane; c < 80; c += 32) {
            float v = (c < IN_F) ? __ldg(xr + c) : 0.f;
            __nv_bfloat16 hb = __float2bfloat16(v);
            o[c]      = hb;
            o[80 + c] = __float2bfloat16(v - __bfloat162float(hb));
        }
    }
}

__global__ void degree_kernel(const int* __restrict__ src, const int* __restrict__ dst) {
    int i = blockIdx.x * blockDim.x + threadIdx.x;
    if (i < N_EDGES) {
        atomicAdd(&g_deg_out[src[i]], 1);
        atomicAdd(&g_deg_in [dst[i]], 1);
    }
}

__global__ void norm_kernel() {
    int i = blockIdx.x * blockDim.x + threadIdx.x;
    if (i < N_NODES) {
        g_norm_src[i] = rsqrtf(fmaxf((float)g_deg_out[i], 1.f));
        g_norm_dst[i] = rsqrtf(fmaxf((float)g_deg_in [i], 1.f));
    }
}

// ---------------- CSR build ----------------
__global__ __launch_bounds__(SCAN_B) void scan1_kernel() {
    __shared__ int sh[SCAN_B];
    int i = blockIdx.x * SCAN_B + threadIdx.x;
    int v = (i < N_NODES) ? g_deg_in[i] : 0;
    sh[threadIdx.x] = v;
    __syncthreads();
#pragma unroll
    for (int off = 1; off < SCAN_B; off <<= 1) {
        int t = (threadIdx.x >= off) ? sh[threadIdx.x - off] : 0;
        __syncthreads();
        sh[threadIdx.x] += t;
        __syncthreads();
    }
    if (i < N_NODES) g_row_ptr[i] = sh[threadIdx.x] - v;
    if (threadIdx.x == SCAN_B - 1) g_bsums[blockIdx.x] = sh[threadIdx.x];
}

__global__ __launch_bounds__(256) void scan2_kernel() {
    __shared__ int sh[256];
    int v = (threadIdx.x < N_SCANB) ? g_bsums[threadIdx.x] : 0;
    sh[threadIdx.x] = v;
    __syncthreads();
#pragma unroll
    for (int off = 1; off < 256; off <<= 1) {
        int t = (threadIdx.x >= off) ? sh[threadIdx.x - off] : 0;
        __syncthreads();
        sh[threadIdx.x] += t;
        __syncthreads();
    }
    if (threadIdx.x < N_SCANB) g_bsums[threadIdx.x] = sh[threadIdx.x] - v;
}

__global__ void scan3_kernel() {
    int i = blockIdx.x * blockDim.x + threadIdx.x;
    if (i < N_NODES) {
        int rp = g_row_ptr[i] + g_bsums[i / SCAN_B];
        g_row_ptr[i] = rp;
        g_cursor [i] = rp;
    }
    if (i == 0) g_row_ptr[N_NODES] = N_EDGES;
}

__global__ void build_csr_kernel(const int* __restrict__ src, const int* __restrict__ dst) {
    int e = blockIdx.x * blockDim.x + threadIdx.x;
    if (e < N_EDGES) {
        int pos = atomicAdd(&g_cursor[dst[e]], 1);
        g_csr_src[pos] = src[e];
    }
}

// ---------------- SpMM gather: one warp/node ----------------
__global__ __launch_bounds__(256) void gather_kernel() {
    int n    = (blockIdx.x * blockDim.x + threadIdx.x) >> 5;
    int lane = threadIdx.x & 31;
    if (n >= N_NODES) return;
    int e0 = __ldg(&g_row_ptr[n]);
    int e1 = __ldg(&g_row_ptr[n + 1]);
    float acc[8];
#pragma unroll
    for (int j = 0; j < 8; j++) acc[j] = 0.f;

    int e = e0;
    for (; e + 4 <= e1; e += 4) {
        int i0 = __ldg(&g_csr_src[e]);
        int i1 = __ldg(&g_csr_src[e + 1]);
        int i2 = __ldg(&g_csr_src[e + 2]);
        int i3 = __ldg(&g_csr_src[e + 3]);
        uint4 r0 = *reinterpret_cast<const uint4*>((const char*)g_h + (size_t)i0 * 512 + lane * 16);
        uint4 r1 = *reinterpret_cast<const uint4*>((const char*)g_h + (size_t)i1 * 512 + lane * 16);
        uint4 r2 = *reinterpret_cast<const uint4*>((const char*)g_h + (size_t)i2 * 512 + lane * 16);
        uint4 r3 = *reinterpret_cast<const uint4*>((const char*)g_h + (size_t)i3 * 512 + lane * 16);
        const uint32_t* p0 = &r0.x;
        const uint32_t* p1 = &r1.x;
        const uint32_t* p2 = &r2.x;
        const uint32_t* p3 = &r3.x;
#pragma unroll
        for (int q = 0; q < 4; q++) {
            __nv_bfloat162 u0 = *reinterpret_cast<const __nv_bfloat162*>(&p0[q]);
            __nv_bfloat162 u1 = *reinterpret_cast<const __nv_bfloat162*>(&p1[q]);
            __nv_bfloat162 u2 = *reinterpret_cast<const __nv_bfloat162*>(&p2[q]);
            __nv_bfloat162 u3 = *reinterpret_cast<const __nv_bfloat162*>(&p3[q]);
            acc[2 * q]     += (__bfloat162float(u0.x) + __bfloat162float(u1.x))
                            + (__bfloat162float(u2.x) + __bfloat162float(u3.x));
            acc[2 * q + 1] += (__bfloat162float(u0.y) + __bfloat162float(u1.y))
                            + (__bfloat162float(u2.y) + __bfloat162float(u3.y));
        }
    }
    for (; e < e1; e++) {
        int a = __ldg(&g_csr_src[e]);
        uint4 ra = *reinterpret_cast<const uint4*>((const char*)g_h + (size_t)a * 512 + lane * 16);
        const uint32_t* pa = &ra.x;
#pragma unroll
        for (int q = 0; q < 4; q++) {
            __nv_bfloat162 ua = *reinterpret_cast<const __nv_bfloat162*>(&pa[q]);
            acc[2 * q]     += __bfloat162float(ua.x);
            acc[2 * q + 1] += __bfloat162float(ua.y);
        }
    }
    float nd = __ldg(&g_norm_dst[n]);
    float w[8];
#pragma unroll
    for (int j = 0; j < 8; j++) {
        float other = __shfl_down_sync(0xffffffffu, acc[j], 16);
        w[j] = (acc[j] + other) * nd;
    }
    if (lane < 16) {
        __nv_bfloat16* rowp = g_agg + (size_t)n * 256;
#pragma unroll
        for (int q = 0; q < 4; q++)
            split_store2(w[2 * q], w[2 * q + 1],
                         rowp + lane * 8 + 2 * q,
                         rowp + 128 + lane * 8 + 2 * q);
    }
}

// ---------------- persistent HMMA GEMM: W staged once, A double-buffered ----------------
// smem: [0..48) 3 mbarriers (A0, A1, W), [64..576) bias, data from 1024.
template<int KSTEPS, int TROWB, int LOOFF, int ROWB>
__global__ __launch_bounds__(256)
void tgemm_kernel(const uint8_t* __restrict__ A8,
                  const uint8_t* __restrict__ W8,
                  const float* __restrict__ bias,
                  const float* __restrict__ out_scale,
                  __nv_bfloat16* __restrict__ o,
                  const int* __restrict__ gids)
{
    extern __shared__ char smem[];
    const int OFF_W  = 1024;
    const int OFF_A0 = OFF_W + 128 * TROWB;
    const int OFF_A1 = OFF_A0 + 128 * TROWB;
    uint32_t sb = smem_u32(smem);
    const int tid = threadIdx.x, wid = tid >> 5, lane = tid & 31;

    if (tid < 3)
        asm volatile("mbarrier.init.shared.b64 [%0], %1;"
                     :: "r"(sb + tid * 16), "r"(1u) : "memory");
    if (tid < 128) ((float*)(smem + 64))[tid] = bias[tid];
    __syncthreads();

    // stage W (once) + first A tile
    auto prefetch = [&](uint32_t mb, uint32_t dstOff, const uint8_t* src, int nrows) {
        asm volatile("mbarrier.arrive.expect_tx.shared.b64 _, [%0], %1;"
                     :: "r"(mb), "r"((uint32_t)(nrows * ROWB)) : "memory");
        for (int row = 0; row < nrows; row++)
            asm volatile("cp.async.bulk.shared::cluster.global.mbarrier::complete_tx::bytes "
                         "[%0], [%1], %2, [%3];"
                         :: "r"(sb + dstOff + row * TROWB), "l"(src + (size_t)row * ROWB),
                            "r"((uint32_t)ROWB), "r"(mb) : "memory");
    };

    int t0 = blockIdx.x;                      // first tile for this CTA
    if (tid == 0) {
        prefetch(sb + 32, OFF_W, W8, 128);
        if (t0 < NTILES)
            prefetch(sb + 0, OFF_A0, A8 + (size_t)t0 * 128 * ROWB,
                     min(128, N_NODES - t0 * 128));
    }
    mbar_wait(sb + 32, 0);                    // W ready

    const int wm = wid >> 1, wn = wid & 1;
    const int r0 = wm * 32, n0 = wn * 64;
    const int arow = lane & 15;
    const int akb  = (lane >> 4) << 4;
    const int bn   = (lane & 7) + ((lane >> 4) << 3);
    const int bkb  = ((lane >> 3) & 1) << 4;
    const float* bs = (const float*)(smem + 64);
    const int cp = n0 + (lane & 3) * 2;

    // preload W fragments once (reused for every tile)
    uint32_t bh[KSTEPS][8][2], bl[KSTEPS][8][2];
#pragma unroll
    for (int ks = 0; ks < KSTEPS; ks++)
#pragma unroll
        for (int jp = 0; jp < 4; jp++) {
            uint32_t bd = sb + OFF_W + (uint32_t)(n0 + jp * 16 + bn) * TROWB + ks * 32 + bkb;
            uint32_t r[4];
            LDSM4(r, bd);
            bh[ks][2 * jp][0] = r[0]; bh[ks][2 * jp][1] = r[1];
            bh[ks][2 * jp + 1][0] = r[2]; bh[ks][2 * jp + 1][1] = r[3];
            LDSM4(r, bd + LOOFF);
            bl[ks][2 * jp][0] = r[0]; bl[ks][2 * jp][1] = r[1];
            bl[ks][2 * jp + 1][0] = r[2]; bl[ks][2 * jp + 1][1] = r[3];
        }

    int cur = 0;
    uint32_t ph[2] = {0u, 0u};
    for (int t = t0; t < NTILES; t += NSM) {
        __syncthreads();   // all warps done reading buf cur^1 (previous tile)
        int nxt = t + NSM;
        if (nxt < NTILES && tid == 0)
            prefetch(sb + (cur ^ 1) * 16, (cur ? OFF_A0 : OFF_A1),
                     A8 + (size_t)nxt * 128 * ROWB, min(128, N_NODES - nxt * 128));

        mbar_wait(sb + cur * 16, ph[cur]);
        ph[cur] ^= 1;
        const int OFF_A = cur ? OFF_A1 : OFF_A0;
        const int row0 = t * 128;

        float acc[2][8][4];
#pragma unroll
        for (int m = 0; m < 2; m++)
#pragma unroll
            for (int j = 0; j < 8; j++)
#pragma unroll
                for (int q = 0; q < 4; q++) acc[m][j][q] = 0.f;

#pragma unroll
        for (int ks = 0; ks < KSTEPS; ks++) {
            uint32_t ah[2][4], al[2][4];
#pragma unroll
            for (int m = 0; m < 2; m++) {
                uint32_t ad = sb + OFF_A + (uint32_t)(r0 + m * 16 + arow) * TROWB + ks * 32 + akb;
                LDSM4(ah[m], ad);
                LDSM4(al[m], ad + LOOFF);
            }
#pragma unroll
            for (int m = 0; m < 2; m++)
#pragma unroll
                for (int j = 0; j < 8; j++) {
                    MMA16816(acc[m][j], ah[m], bh[ks][j]);
                    MMA16816(acc[m][j], ah[m], bl[ks][j]);
                    MMA16816(acc[m][j], al[m], bh[ks][j]);
                }
        }

        // ---- epilogue ----
        if (gids) {
            int curg = -1;
            float p[16];
#pragma unroll
            for (int m = 0; m < 2; m++) {
#pragma unroll
                for (int hf = 0; hf < 2; hf++) {
                    int gr = row0 + r0 + m * 16 + hf * 8 + (lane >> 2);
                    if (gr >= N_NODES) continue;
                    int g = __ldg(gids + gr);
                    float v[16];
#pragma unroll
                    for (int j = 0; j < 8; j++) {
                        int c = cp + j * 8;
                        v[2 * j]     = fast_silu(acc[m][j][hf * 2 + 0] + bs[c]);
                        v[2 * j + 1] = fast_silu(acc[m][j][hf * 2 + 1] + bs[c + 1]);
                    }
                    if (g == curg) {
#pragma unroll
                        for (int k = 0; k < 16; k++) p[k] += v[k];
                    } else {
                        if (curg >= 0) {
                            float* pb = g_pooled + (size_t)curg * 128 + cp;
#pragma unroll
                            for (int j = 0; j < 8; j++)
                                asm volatile("red.global.add.v2.f32 [%0], {%1,%2};"
                                             :: "l"(pb + j * 8), "f"(p[2 * j]), "f"(p[2 * j + 1])
                                             : "memory");
                        }
                        curg = g;
#pragma unroll
                        for (int k = 0; k < 16; k++) p[k] = v[k];
                    }
                }
            }
            if (curg >= 0) {
                float* pb = g_pooled + (size_t)curg * 128 + cp;
#pragma unroll
                for (int j = 0; j < 8; j++)
                    asm volatile("red.global.add.v2.f32 [%0], {%1,%2};"
                                 :: "l"(pb + j * 8), "f"(p[2 * j]), "f"(p[2 * j + 1])
                                 : "memory");
            }
        } else {
#pragma unroll
            for (int m = 0; m < 2; m++) {
#pragma unroll
                for (int hf = 0; hf < 2; hf++) {
                    int gr = row0 + r0 + m * 16 + hf * 8 + (lane >> 2);
                    if (gr >= N_NODES) continue;
                    float os = out_scale ? __ldg(out_scale + gr) : 1.f;
                    __nv_bfloat16* rowp = o + (size_t)gr * 256;
#pragma unroll
                    for (int j = 0; j < 8; j++) {
                        int c = cp + j * 8;
                        float va = fast_silu(acc[m][j][hf * 2 + 0] + bs[c]) * os;
                        float vb = fast_silu(acc[m][j][hf * 2 + 1] + bs[c + 1]) * os;
                        split_store2(va, vb, rowp + c, rowp + 128 + c);
                    }
                }
            }
        }
        cur ^= 1;
    }
    __syncthreads();
    if (tid < 3)
        asm volatile("mbarrier.inval.shared.b64 [%0];" :: "r"(sb + tid * 16) : "memory");
}

// ---------------- FFMA GEMM (final w_ff only) ----------------
__global__ __launch_bounds__(256, 2)
void gemm_kernel(const float* __restrict__ A, int M,
                 const float* __restrict__ B, const float* __restrict__ bias,
                 float* __restrict__ C)
{
    __shared__ unsigned long long As2[2][8][128];
    __shared__ float              Bs [2][8][128];

    const int t    = threadIdx.x;
    const int tx   = t & 15;
    const int ty   = t >> 4;
    const int row0 = blockIdx.x * 128;

    const int arow = t >> 1;
    const int akl  = (t & 1) * 4;
    const int brow = t >> 5;
    const int bcol = (t & 31) * 4;
    const int gr   = row0 + arow;

    unsigned long long acc[8][4];
#pragma unroll
    for (int i = 0; i < 8; i++)
#pragma unroll
        for (int j = 0; j < 4; j++) acc[i][j] = 0ULL;

    float4 aReg, bReg;
    auto load_regs = [&](int k0) {
        aReg = (gr < M) ? *reinterpret_cast<const float4*>(A + (size_t)gr * 128 + k0 + akl)
                        : make_float4(0.f, 0.f, 0.f, 0.f);
        bReg = *reinterpret_cast<const float4*>(B + (size_t)(k0 + brow) * 128 + bcol);
    };
    auto store_smem = [&](int buf) {
        unsigned long long p0, p1, p2, p3;
        asm("mov.b64 %0, {%1, %1};" : "=l"(p0) : "f"(aReg.x));
        asm("mov.b64 %0, {%1, %1};" : "=l"(p1) : "f"(aReg.y));
        asm("mov.b64 %0, {%1, %1};" : "=l"(p2) : "f"(aReg.z));
        asm("mov.b64 %0, {%1, %1};" : "=l"(p3) : "f"(aReg.w));
        As2[buf][akl + 0][arow] = p0;
        As2[buf][akl + 1][arow] = p1;
        As2[buf][akl + 2][arow] = p2;
        As2[buf][akl + 3][arow] = p3;
        *reinterpret_cast<float4*>(&Bs[buf][brow][bcol]) = bReg;
    };

    load_regs(0);
    store_smem(0);
    __syncthreads();
    int cur = 0;
    for (int c = 0; c < 16; c++) {
        const bool more = (c + 1 < 16);
        if (more) load_regs((c + 1) * 8);
#pragma unroll
        for (int k = 0; k < 8; k++) {
            ulonglong2 u0 = *reinterpret_cast<const ulonglong2*>(&Bs[cur][k][tx * 4]);
            ulonglong2 u1 = *reinterpret_cast<const ulonglong2*>(&Bs[cur][k][64 + tx * 4]);
            unsigned long long bp[4] = {u0.x, u0.y, u1.x, u1.y};
            const ulonglong2* ap = reinterpret_cast<const ulonglong2*>(&As2[cur][k][ty * 8]);
            ulonglong2 a01 = ap[0], a23 = ap[1], a45 = ap[2], a67 = ap[3];
            unsigned long long av[8] = {a01.x, a01.y, a23.x, a23.y,
                                        a45.x, a45.y, a67.x, a67.y};
#pragma unroll
            for (int i = 0; i < 8; i++)
#pragma unroll
                for (int j = 0; j < 4; j++)
                    asm("fma.rn.f32x2 %0, %1, %2, %0;"
                        : "+l"(acc[i][j]) : "l"(av[i]), "l"(bp[j]));
        }
        if (more) store_smem(cur ^ 1);
        __syncthreads();
        cur ^= 1;
    }

    float4 bb0 = *reinterpret_cast<const float4*>(bias + tx * 4);
    float4 bb1 = *reinterpret_cast<const float4*>(bias + 64 + tx * 4);
    float bia[8] = {bb0.x, bb0.y, bb0.z, bb0.w, bb1.x, bb1.y, bb1.z, bb1.w};
#pragma unroll
    for (int i = 0; i < 8; i++) {
        int r = row0 + ty * 8 + i;
        if (r >= M) break;
        float v[8];
#pragma unroll
        for (int j = 0; j < 4; j++) {
            float lo, hi;
            asm("mov.b64 {%0, %1}, %2;" : "=f"(lo), "=f"(hi) : "l"(acc[i][j]));
            v[2 * j] = lo + bia[2 * j];
            v[2 * j + 1] = hi + bia[2 * j + 1];
        }
        *reinterpret_cast<float4*>(C + (size_t)r * 128 + tx * 4) =
            make_float4(v[0], v[1], v[2], v[3]);
        *reinterpret_cast<float4*>(C + (size_t)r * 128 + 64 + tx * 4) =
            make_float4(v[4], v[5], v[6], v[7]);
    }
}

// ---------------- launch ----------------
extern "C" void kernel_launch(void* const* d_in, const int* in_sizes, int n_in,
                              void* d_out, int out_size) {
    const float* x     = (const float*)d_in[0];
    const int*   src   = (const int*)  d_in[1];
    const int*   dst   = (const int*)  d_in[2];
    const int*   gid   = (const int*)  d_in[3];
    const float* w_in  = (const float*)d_in[4];
    const float* b_in  = (const float*)d_in[5];
    const float* gw    = (const float*)d_in[6];
    const float* gb    = (const float*)d_in[7];
    const float* w_out = (const float*)d_in[8];
    const float* b_out = (const float*)d_in[9];
    const float* w_ff  = (const float*)d_in[10];
    const float* b_ff  = (const float*)d_in[11];
    float* out = (float*)d_out;

    float *pooled, *nsrc;
    __nv_bfloat16 *h, *agg, *xs, *w, *win;
    cudaGetSymbolAddress((void**)&pooled, g_pooled);
    cudaGetSymbolAddress((void**)&nsrc,   g_norm_src);
    cudaGetSymbolAddress((void**)&h,      g_h);
    cudaGetSymbolAddress((void**)&agg,    g_agg);
    cudaGetSymbolAddress((void**)&xs,     g_xs);
    cudaGetSymbolAddress((void**)&w,      g_w);
    cudaGetSymbolAddress((void**)&win,    g_win);

    auto tg128 = tgemm_kernel<8, 528, 256, 512>;
    auto tg80  = tgemm_kernel<5, 336, 160, 320>;
    const int SM128 = 1024 + 3 * 128 * 528;   // 203,776
    const int SM80  = 1024 + 3 * 128 * 336;   // 130,048
    cudaFuncSetAttribute(tg128, cudaFuncAttributeMaxDynamicSharedMemorySize, SM128);
    cudaFuncSetAttribute(tg80,  cudaFuncAttributeMaxDynamicSharedMemorySize, SM80);

    // prep (1), degree (2), norm (3), tg80 (4) <- profiled launch
    prepx_kernel<<<(N_NODES * 32 + 255) / 256, 256>>>(gw, w_out, w_in, x);
    degree_kernel<<<(N_EDGES + 255) / 256, 256>>>(src, dst);
    norm_kernel<<<(N_NODES + 255) / 256, 256>>>();

    // h = silu(xs @ w_in + b_in) * norm_src   (persistent HMMA, K=80)
    tg80<<<NSM, 256, SM80>>>((const uint8_t*)xs, (const uint8_t*)win,
                             b_in, nsrc, h, nullptr);

    scan1_kernel<<<N_SCANB, SCAN_B>>>();
    scan2_kernel<<<1, 256>>>();
    scan3_kernel<<<(N_NODES + 255) / 256, 256>>>();
    build_csr_kernel<<<(N_EDGES + 255) / 256, 256>>>(src, dst);

    for (int l = 0; l < 3; l++) {
        gather_kernel<<<(N_NODES * 32 + 255) / 256, 256>>>();
        tg128<<<NSM, 256, SM128>>>((const uint8_t*)agg,
                                   (const uint8_t*)(w + (size_t)l * 128 * 256),
                                   gb + (size_t)l * HID, (l < 2) ? nsrc : nullptr,
                                   h, nullptr);
    }

    // pool: pooled[gid] += silu(h @ w_out + b_out)
    tg128<<<NSM, 256, SM128>>>((const uint8_t*)h,
                               (const uint8_t*)(w + (size_t)3 * 128 * 256),
                               b_out, nullptr, nullptr, gid);

    // out = pooled @ w_ff + b_ff  (fp32 FFMA)
    gemm_kernel<<<(N_GRAPHS + 127) / 128, 256>>>(pooled, N_GRAPHS, w_ff, b_ff, out);
}

// round 16
// speedup vs baseline: 1.1520x; 1.1520x over previous
#include <cuda_runtime.h>
#include <cuda_bf16.h>
#include <cstdint>

#define N_NODES  200000
#define N_EDGES  1600000
#define N_GRAPHS 10000
#define IN_F     74
#define HID      128

#define SCAN_B   1024
#define N_SCANB  ((N_NODES + SCAN_B - 1) / SCAN_B)   // 196
#define NSM      152
#define NTILES   ((N_NODES + 127) / 128)             // 1563

// interleaved split rows: h/agg = 256 bf16 [hi128|lo128] = 512B; x = 160 bf16 [hi80|lo80] = 320B
__device__ __align__(16) __nv_bfloat16 g_h  [(size_t)N_NODES * 256];
__device__ __align__(16) __nv_bfloat16 g_agg[(size_t)N_NODES * 256];
__device__ __align__(16) __nv_bfloat16 g_xs [(size_t)N_NODES * 160];
__device__ __align__(16) __nv_bfloat16 g_w  [4 * HID * 256];     // [l][n][hi128|lo128], W^T
__device__ __align__(16) __nv_bfloat16 g_win[HID * 160];         // w_in^T [n][hi80|lo80]
__device__ __align__(16) int   g_deg_out[N_NODES];
__device__ __align__(16) int   g_deg_in [N_NODES];
__device__ __align__(16) float g_norm_src[N_NODES];
__device__ __align__(16) float g_norm_dst[N_NODES];
__device__ __align__(16) float g_pooled[(size_t)N_GRAPHS * HID];
__device__ __align__(16) int   g_row_ptr[N_NODES + 1];
__device__ __align__(16) int   g_cursor [N_NODES];
__device__ __align__(16) int   g_csr_src[N_EDGES];
__device__ __align__(16) int   g_bsums  [N_SCANB];

__device__ __forceinline__ float fast_silu(float w) {
    float t, r;
    asm("ex2.approx.f32 %0, %1;" : "=f"(t) : "f"(-1.4426950408889634f * w));
    asm("rcp.approx.f32 %0, %1;" : "=f"(r) : "f"(1.f + t));
    return w * r;
}

__device__ __forceinline__ uint32_t smem_u32(const void* p) {
    uint32_t a;
    asm("{ .reg .u64 t; cvta.to.shared.u64 t, %1; cvt.u32.u64 %0, t; }" : "=r"(a) : "l"(p));
    return a;
}

__device__ __forceinline__ void mbar_wait(uint32_t mb, uint32_t parity) {
    asm volatile("{\n\t.reg .pred P1;\n\t"
                 "WL_%=:\n\t"
                 "mbarrier.try_wait.parity.acquire.cta.shared::cta.b64 P1, [%0], %1, 0x989680;\n\t"
                 "@P1 bra.uni WD_%=;\n\t"
                 "bra.uni WL_%=;\n\t"
                 "WD_%=:\n\t}" :: "r"(mb), "r"(parity) : "memory");
}

#define LDSM4(r, addr)                                                          \
    asm volatile("ldmatrix.sync.aligned.m8n8.x4.shared.b16 {%0,%1,%2,%3}, [%4];" \
                 : "=r"((r)[0]), "=r"((r)[1]), "=r"((r)[2]), "=r"((r)[3])        \
                 : "r"(addr))

#define MMA16816(c, a, b)                                                        \
    asm volatile("mma.sync.aligned.m16n8k16.row.col.f32.bf16.bf16.f32 "          \
                 "{%0,%1,%2,%3}, {%4,%5,%6,%7}, {%8,%9}, {%0,%1,%2,%3};"         \
                 : "+f"((c)[0]), "+f"((c)[1]), "+f"((c)[2]), "+f"((c)[3])        \
                 : "r"((a)[0]), "r"((a)[1]), "r"((a)[2]), "r"((a)[3]),           \
                   "r"((b)[0]), "r"((b)[1]))

__device__ __forceinline__ void split_store2(float va, float vb, __nv_bfloat16* hi_p,
                                             __nv_bfloat16* lo_p) {
    __nv_bfloat16 ha = __float2bfloat16(va);
    __nv_bfloat16 hb = __float2bfloat16(vb);
    *reinterpret_cast<uint32_t*>(hi_p) =
        (uint32_t)__bfloat16_as_ushort(ha) | ((uint32_t)__bfloat16_as_ushort(hb) << 16);
    *reinterpret_cast<uint32_t*>(lo_p) =
        (uint32_t)__bfloat16_as_ushort(__float2bfloat16(va - __bfloat162float(ha)))
      | ((uint32_t)__bfloat16_as_ushort(__float2bfloat16(vb - __bfloat162float(hb))) << 16);
}

// ---------------- fused prep: zeros + weight split/transpose + x split -----------------
__global__ __launch_bounds__(256) void prepx_kernel(const float* __restrict__ gw,
                                                    const float* __restrict__ w_out,
                                                    const float* __restrict__ w_in,
                                                    const float* __restrict__ x) {
    int i = blockIdx.x * blockDim.x + threadIdx.x;
    if (i < N_NODES / 4) {
        reinterpret_cast<int4*>(g_deg_out)[i] = make_int4(0, 0, 0, 0);
        reinterpret_cast<int4*>(g_deg_in )[i] = make_int4(0, 0, 0, 0);
    }
    if (i < N_GRAPHS * HID / 4)
        reinterpret_cast<float4*>(g_pooled)[i] = make_float4(0.f, 0.f, 0.f, 0.f);
    if (i < 4 * HID * HID) {
        int l = i >> 14, n = (i >> 7) & 127, k = i & 127;
        float v = (l < 3) ? gw[l * HID * HID + k * HID + n] : w_out[k * HID + n];
        __nv_bfloat16 hb = __float2bfloat16(v);
        size_t base = ((size_t)(l * 128 + n)) * 256;
        g_w[base + k]       = hb;
        g_w[base + 128 + k] = __float2bfloat16(v - __bfloat162float(hb));
    }
    if (i < HID * 80) {
        int n = i / 80, k = i % 80;
        float v = (k < IN_F) ? w_in[k * HID + n] : 0.f;
        __nv_bfloat16 hb = __float2bfloat16(v);
        g_win[n * 160 + k]      = hb;
        g_win[n * 160 + 80 + k] = __float2bfloat16(v - __bfloat162float(hb));
    }
    // x split: one warp per row
    int row  = i >> 5;
    int lane = i & 31;
    if (row < N_NODES) {
        const float* xr = x + (size_t)row * IN_F;
        __nv_bfloat16* o = g_xs + (size_t)row * 160;
#pragma unroll
        for (int c = lane; c < 80; c += 32) {
            float v = (c < IN_F) ? __ldg(xr + c) : 0.f;
            __nv_bfloat16 hb = __float2bfloat16(v);
            o[c]      = hb;
            o[80 + c] = __float2bfloat16(v - __bfloat162float(hb));
        }
    }
}

__global__ void degree_kernel(const int* __restrict__ src, const int* __restrict__ dst) {
    int i = blockIdx.x * blockDim.x + threadIdx.x;
    if (i < N_EDGES) {
        atomicAdd(&g_deg_out[src[i]], 1);
        atomicAdd(&g_deg_in [dst[i]], 1);
    }
}

__global__ void norm_kernel() {
    int i = blockIdx.x * blockDim.x + threadIdx.x;
    if (i < N_NODES) {
        g_norm_src[i] = rsqrtf(fmaxf((float)g_deg_out[i], 1.f));
        g_norm_dst[i] = rsqrtf(fmaxf((float)g_deg_in [i], 1.f));
    }
}

// ---------------- CSR build ----------------
__global__ __launch_bounds__(SCAN_B) void scan1_kernel() {
    __shared__ int sh[SCAN_B];
    int i = blockIdx.x * SCAN_B + threadIdx.x;
    int v = (i < N_NODES) ? g_deg_in[i] : 0;
    sh[threadIdx.x] = v;
    __syncthreads();
#pragma unroll
    for (int off = 1; off < SCAN_B; off <<= 1) {
        int t = (threadIdx.x >= off) ? sh[threadIdx.x - off] : 0;
        __syncthreads();
        sh[threadIdx.x] += t;
        __syncthreads();
    }
    if (i < N_NODES) g_row_ptr[i] = sh[threadIdx.x] - v;
    if (threadIdx.x == SCAN_B - 1) g_bsums[blockIdx.x] = sh[threadIdx.x];
}

__global__ __launch_bounds__(256) void scan2_kernel() {
    __shared__ int sh[256];
    int v = (threadIdx.x < N_SCANB) ? g_bsums[threadIdx.x] : 0;
    sh[threadIdx.x] = v;
    __syncthreads();
#pragma unroll
    for (int off = 1; off < 256; off <<= 1) {
        int t = (threadIdx.x >= off) ? sh[threadIdx.x - off] : 0;
        __syncthreads();
        sh[threadIdx.x] += t;
        __syncthreads();
    }
    if (threadIdx.x < N_SCANB) g_bsums[threadIdx.x] = sh[threadIdx.x] - v;
}

__global__ void scan3_kernel() {
    int i = blockIdx.x * blockDim.x + threadIdx.x;
    if (i < N_NODES) {
        int rp = g_row_ptr[i] + g_bsums[i / SCAN_B];
        g_row_ptr[i] = rp;
        g_cursor [i] = rp;
    }
    if (i == 0) g_row_ptr[N_NODES] = N_EDGES;
}

__global__ void build_csr_kernel(const int* __restrict__ src, const int* __restrict__ dst) {
    int e = blockIdx.x * blockDim.x + threadIdx.x;
    if (e < N_EDGES) {
        int pos = atomicAdd(&g_cursor[dst[e]], 1);
        g_csr_src[pos] = src[e];
    }
}

// ---------------- SpMM gather: one warp/node ----------------
__global__ __launch_bounds__(256) void gather_kernel() {
    int n    = (blockIdx.x * blockDim.x + threadIdx.x) >> 5;
    int lane = threadIdx.x & 31;
    if (n >= N_NODES) return;
    int e0 = __ldg(&g_row_ptr[n]);
    int e1 = __ldg(&g_row_ptr[n + 1]);
    float acc[8];
#pragma unroll
    for (int j = 0; j < 8; j++) acc[j] = 0.f;

    int e = e0;
    for (; e + 4 <= e1; e += 4) {
        int i0 = __ldg(&g_csr_src[e]);
        int i1 = __ldg(&g_csr_src[e + 1]);
        int i2 = __ldg(&g_csr_src[e + 2]);
        int i3 = __ldg(&g_csr_src[e + 3]);
        uint4 r0 = *reinterpret_cast<const uint4*>((const char*)g_h + (size_t)i0 * 512 + lane * 16);
        uint4 r1 = *reinterpret_cast<const uint4*>((const char*)g_h + (size_t)i1 * 512 + lane * 16);
        uint4 r2 = *reinterpret_cast<const uint4*>((const char*)g_h + (size_t)i2 * 512 + lane * 16);
        uint4 r3 = *reinterpret_cast<const uint4*>((const char*)g_h + (size_t)i3 * 512 + lane * 16);
        const uint32_t* p0 = &r0.x;
        const uint32_t* p1 = &r1.x;
        const uint32_t* p2 = &r2.x;
        const uint32_t* p3 = &r3.x;
#pragma unroll
        for (int q = 0; q < 4; q++) {
            __nv_bfloat162 u0 = *reinterpret_cast<const __nv_bfloat162*>(&p0[q]);
            __nv_bfloat162 u1 = *reinterpret_cast<const __nv_bfloat162*>(&p1[q]);
            __nv_bfloat162 u2 = *reinterpret_cast<const __nv_bfloat162*>(&p2[q]);
            __nv_bfloat162 u3 = *reinterpret_cast<const __nv_bfloat162*>(&p3[q]);
            acc[2 * q]     += (__bfloat162float(u0.x) + __bfloat162float(u1.x))
                            + (__bfloat162float(u2.x) + __bfloat162float(u3.x));
            acc[2 * q + 1] += (__bfloat162float(u0.y) + __bfloat162float(u1.y))
                            + (__bfloat162float(u2.y) + __bfloat162float(u3.y));
        }
    }
    for (; e < e1; e++) {
        int a = __ldg(&g_csr_src[e]);
        uint4 ra = *reinterpret_cast<const uint4*>((const char*)g_h + (size_t)a * 512 + lane * 16);
        const uint32_t* pa = &ra.x;
#pragma unroll
        for (int q = 0; q < 4; q++) {
            __nv_bfloat162 ua = *reinterpret_cast<const __nv_bfloat162*>(&pa[q]);
            acc[2 * q]     += __bfloat162float(ua.x);
            acc[2 * q + 1] += __bfloat162float(ua.y);
        }
    }
    float nd = __ldg(&g_norm_dst[n]);
    float w[8];
#pragma unroll
    for (int j = 0; j < 8; j++) {
        float other = __shfl_down_sync(0xffffffffu, acc[j], 16);
        w[j] = (acc[j] + other) * nd;
    }
    if (lane < 16) {
        __nv_bfloat16* rowp = g_agg + (size_t)n * 256;
#pragma unroll
        for (int q = 0; q < 4; q++)
            split_store2(w[2 * q], w[2 * q + 1],
                         rowp + lane * 8 + 2 * q,
                         rowp + 128 + lane * 8 + 2 * q);
    }
}

// ---------------- persistent HMMA GEMM: W staged once (SMEM), A double-buffered --------
// W fragments re-read from SMEM via ldmatrix each tile (NO register residency -> no spill).
// smem: [0..48) 3 mbarriers (A0, A1, W), [64..576) bias, data from 1024.
template<int KSTEPS, int TROWB, int LOOFF, int ROWB>
__global__ __launch_bounds__(256)
void tgemm_kernel(const uint8_t* __restrict__ A8,
                  const uint8_t* __restrict__ W8,
                  const float* __restrict__ bias,
                  const float* __restrict__ out_scale,
                  __nv_bfloat16* __restrict__ o,
                  const int* __restrict__ gids)
{
    extern __shared__ char smem[];
    const int OFF_W  = 1024;
    const int OFF_A0 = OFF_W + 128 * TROWB;
    const int OFF_A1 = OFF_A0 + 128 * TROWB;
    uint32_t sb = smem_u32(smem);
    const int tid = threadIdx.x, wid = tid >> 5, lane = tid & 31;

    if (tid < 3)
        asm volatile("mbarrier.init.shared.b64 [%0], %1;"
                     :: "r"(sb + tid * 16), "r"(1u) : "memory");
    if (tid < 128) ((float*)(smem + 64))[tid] = bias[tid];
    __syncthreads();

    auto prefetch = [&](uint32_t mb, uint32_t dstOff, const uint8_t* src, int nrows) {
        asm volatile("mbarrier.arrive.expect_tx.shared.b64 _, [%0], %1;"
                     :: "r"(mb), "r"((uint32_t)(nrows * ROWB)) : "memory");
        for (int row = 0; row < nrows; row++)
            asm volatile("cp.async.bulk.shared::cluster.global.mbarrier::complete_tx::bytes "
                         "[%0], [%1], %2, [%3];"
                         :: "r"(sb + dstOff + row * TROWB), "l"(src + (size_t)row * ROWB),
                            "r"((uint32_t)ROWB), "r"(mb) : "memory");
    };

    int t0 = blockIdx.x;
    if (tid == 0) {
        prefetch(sb + 32, OFF_W, W8, 128);
        if (t0 < NTILES)
            prefetch(sb + 0, OFF_A0, A8 + (size_t)t0 * 128 * ROWB,
                     min(128, N_NODES - t0 * 128));
    }
    mbar_wait(sb + 32, 0);                    // W resident in SMEM for the whole kernel

    const int wm = wid >> 1, wn = wid & 1;
    const int r0 = wm * 32, n0 = wn * 64;
    const int arow = lane & 15;
    const int akb  = (lane >> 4) << 4;
    const int bn   = (lane & 7) + ((lane >> 4) << 3);
    const int bkb  = ((lane >> 3) & 1) << 4;
    const float* bs = (const float*)(smem + 64);
    const int cp = n0 + (lane & 3) * 2;

    int cur = 0;
    uint32_t ph[2] = {0u, 0u};
    for (int t = t0; t < NTILES; t += NSM) {
        __syncthreads();   // all warps done reading buf cur^1 (previous tile)
        int nxt = t + NSM;
        if (nxt < NTILES && tid == 0)
            prefetch(sb + (cur ^ 1) * 16, (cur ? OFF_A0 : OFF_A1),
                     A8 + (size_t)nxt * 128 * ROWB, min(128, N_NODES - nxt * 128));

        mbar_wait(sb + cur * 16, ph[cur]);
        ph[cur] ^= 1;
        const int OFF_A = cur ? OFF_A1 : OFF_A0;
        const int row0 = t * 128;

        float acc[2][8][4];
#pragma unroll
        for (int m = 0; m < 2; m++)
#pragma unroll
            for (int j = 0; j < 8; j++)
#pragma unroll
                for (int q = 0; q < 4; q++) acc[m][j][q] = 0.f;

#pragma unroll
        for (int ks = 0; ks < KSTEPS; ks++) {
            uint32_t ah[2][4], al[2][4], bh[8][2], bl[8][2];
#pragma unroll
            for (int m = 0; m < 2; m++) {
                uint32_t ad = sb + OFF_A + (uint32_t)(r0 + m * 16 + arow) * TROWB + ks * 32 + akb;
                LDSM4(ah[m], ad);
                LDSM4(al[m], ad + LOOFF);
            }
#pragma unroll
            for (int jp = 0; jp < 4; jp++) {
                uint32_t bd = sb + OFF_W + (uint32_t)(n0 + jp * 16 + bn) * TROWB + ks * 32 + bkb;
                uint32_t r[4];
                LDSM4(r, bd);
                bh[2 * jp][0] = r[0]; bh[2 * jp][1] = r[1];
                bh[2 * jp + 1][0] = r[2]; bh[2 * jp + 1][1] = r[3];
                LDSM4(r, bd + LOOFF);
                bl[2 * jp][0] = r[0]; bl[2 * jp][1] = r[1];
                bl[2 * jp + 1][0] = r[2]; bl[2 * jp + 1][1] = r[3];
            }
#pragma unroll
            for (int m = 0; m < 2; m++)
#pragma unroll
                for (int j = 0; j < 8; j++) {
                    MMA16816(acc[m][j], ah[m], bh[j]);
                    MMA16816(acc[m][j], ah[m], bl[j]);
                    MMA16816(acc[m][j], al[m], bh[j]);
                }
        }

        // ---- epilogue ----
        if (gids) {
            int curg = -1;
            float p[16];
#pragma unroll
            for (int m = 0; m < 2; m++) {
#pragma unroll
                for (int hf = 0; hf < 2; hf++) {
                    int gr = row0 + r0 + m * 16 + hf * 8 + (lane >> 2);
                    if (gr >= N_NODES) continue;
                    int g = __ldg(gids + gr);
                    float v[16];
#pragma unroll
                    for (int j = 0; j < 8; j++) {
                        int c = cp + j * 8;
                        v[2 * j]     = fast_silu(acc[m][j][hf * 2 + 0] + bs[c]);
                        v[2 * j + 1] = fast_silu(acc[m][j][hf * 2 + 1] + bs[c + 1]);
                    }
                    if (g == curg) {
#pragma unroll
                        for (int k = 0; k < 16; k++) p[k] += v[k];
                    } else {
                        if (curg >= 0) {
                            float* pb = g_pooled + (size_t)curg * 128 + cp;
#pragma unroll
                            for (int j = 0; j < 8; j++)
                                asm volatile("red.global.add.v2.f32 [%0], {%1,%2};"
                                             :: "l"(pb + j * 8), "f"(p[2 * j]), "f"(p[2 * j + 1])
                                             : "memory");
                        }
                        curg = g;
#pragma unroll
                        for (int k = 0; k < 16; k++) p[k] = v[k];
                    }
                }
            }
            if (curg >= 0) {
                float* pb = g_pooled + (size_t)curg * 128 + cp;
#pragma unroll
                for (int j = 0; j < 8; j++)
                    asm volatile("red.global.add.v2.f32 [%0], {%1,%2};"
                                 :: "l"(pb + j * 8), "f"(p[2 * j]), "f"(p[2 * j + 1])
                                 : "memory");
            }
        } else {
#pragma unroll
            for (int m = 0; m < 2; m++) {
#pragma unroll
                for (int hf = 0; hf < 2; hf++) {
                    int gr = row0 + r0 + m * 16 + hf * 8 + (lane >> 2);
                    if (gr >= N_NODES) continue;
                    float os = out_scale ? __ldg(out_scale + gr) : 1.f;
                    __nv_bfloat16* rowp = o + (size_t)gr * 256;
#pragma unroll
                    for (int j = 0; j < 8; j++) {
                        int c = cp + j * 8;
                        float va = fast_silu(acc[m][j][hf * 2 + 0] + bs[c]) * os;
                        float vb = fast_silu(acc[m][j][hf * 2 + 1] + bs[c + 1]) * os;
                        split_store2(va, vb, rowp + c, rowp + 128 + c);
                    }
                }
            }
        }
        cur ^= 1;
    }
    __syncthreads();
    if (tid < 3)
        asm volatile("mbarrier.inval.shared.b64 [%0];" :: "r"(sb + tid * 16) : "memory");
}

// ---------------- FFMA GEMM (final w_ff only) ----------------
__global__ __launch_bounds__(256, 2)
void gemm_kernel(const float* __restrict__ A, int M,
                 const float* __restrict__ B, const float* __restrict__ bias,
                 float* __restrict__ C)
{
    __shared__ unsigned long long As2[2][8][128];
    __shared__ float              Bs [2][8][128];

    const int t    = threadIdx.x;
    const int tx   = t & 15;
    const int ty   = t >> 4;
    const int row0 = blockIdx.x * 128;

    const int arow = t >> 1;
    const int akl  = (t & 1) * 4;
    const int brow = t >> 5;
    const int bcol = (t & 31) * 4;
    const int gr   = row0 + arow;

    unsigned long long acc[8][4];
#pragma unroll
    for (int i = 0; i < 8; i++)
#pragma unroll
        for (int j = 0; j < 4; j++) acc[i][j] = 0ULL;

    float4 aReg, bReg;
    auto load_regs = [&](int k0) {
        aReg = (gr < M) ? *reinterpret_cast<const float4*>(A + (size_t)gr * 128 + k0 + akl)
                        : make_float4(0.f, 0.f, 0.f, 0.f);
        bReg = *reinterpret_cast<const float4*>(B + (size_t)(k0 + brow) * 128 + bcol);
    };
    auto store_smem = [&](int buf) {
        unsigned long long p0, p1, p2, p3;
        asm("mov.b64 %0, {%1, %1};" : "=l"(p0) : "f"(aReg.x));
        asm("mov.b64 %0, {%1, %1};" : "=l"(p1) : "f"(aReg.y));
        asm("mov.b64 %0, {%1, %1};" : "=l"(p2) : "f"(aReg.z));
        asm("mov.b64 %0, {%1, %1};" : "=l"(p3) : "f"(aReg.w));
        As2[buf][akl + 0][arow] = p0;
        As2[buf][akl + 1][arow] = p1;
        As2[buf][akl + 2][arow] = p2;
        As2[buf][akl + 3][arow] = p3;
        *reinterpret_cast<float4*>(&Bs[buf][brow][bcol]) = bReg;
    };

    load_regs(0);
    store_smem(0);
    __syncthreads();
    int cur = 0;
    for (int c = 0; c < 16; c++) {
        const bool more = (c + 1 < 16);
        if (more) load_regs((c + 1) * 8);
#pragma unroll
        for (int k = 0; k < 8; k++) {
            ulonglong2 u0 = *reinterpret_cast<const ulonglong2*>(&Bs[cur][k][tx * 4]);
            ulonglong2 u1 = *reinterpret_cast<const ulonglong2*>(&Bs[cur][k][64 + tx * 4]);
            unsigned long long bp[4] = {u0.x, u0.y, u1.x, u1.y};
            const ulonglong2* ap = reinterpret_cast<const ulonglong2*>(&As2[cur][k][ty * 8]);
            ulonglong2 a01 = ap[0], a23 = ap[1], a45 = ap[2], a67 = ap[3];
            unsigned long long av[8] = {a01.x, a01.y, a23.x, a23.y,
                                        a45.x, a45.y, a67.x, a67.y};
#pragma unroll
            for (int i = 0; i < 8; i++)
#pragma unroll
                for (int j = 0; j < 4; j++)
                    asm("fma.rn.f32x2 %0, %1, %2, %0;"
                        : "+l"(acc[i][j]) : "l"(av[i]), "l"(bp[j]));
        }
        if (more) store_smem(cur ^ 1);
        __syncthreads();
        cur ^= 1;
    }

    float4 bb0 = *reinterpret_cast<const float4*>(bias + tx * 4);
    float4 bb1 = *reinterpret_cast<const float4*>(bias + 64 + tx * 4);
    float bia[8] = {bb0.x, bb0.y, bb0.z, bb0.w, bb1.x, bb1.y, bb1.z, bb1.w};
#pragma unroll
    for (int i = 0; i < 8; i++) {
        int r = row0 + ty * 8 + i;
        if (r >= M) break;
        float v[8];
#pragma unroll
        for (int j = 0; j < 4; j++) {
            float lo, hi;
            asm("mov.b64 {%0, %1}, %2;" : "=f"(lo), "=f"(hi) : "l"(acc[i][j]));
            v[2 * j] = lo + bia[2 * j];
            v[2 * j + 1] = hi + bia[2 * j + 1];
        }
        *reinterpret_cast<float4*>(C + (size_t)r * 128 + tx * 4) =
            make_float4(v[0], v[1], v[2], v[3]);
        *reinterpret_cast<float4*>(C + (size_t)r * 128 + 64 + tx * 4) =
            make_float4(v[4], v[5], v[6], v[7]);
    }
}

// ---------------- launch ----------------
extern "C" void kernel_launch(void* const* d_in, const int* in_sizes, int n_in,
                              void* d_out, int out_size) {
    const float* x     = (const float*)d_in[0];
    const int*   src   = (const int*)  d_in[1];
    const int*   dst   = (const int*)  d_in[2];
    const int*   gid   = (const int*)  d_in[3];
    const float* w_in  = (const float*)d_in[4];
    const float* b_in  = (const float*)d_in[5];
    const float* gw    = (const float*)d_in[6];
    const float* gb    = (const float*)d_in[7];
    const float* w_out = (const float*)d_in[8];
    const float* b_out = (const float*)d_in[9];
    const float* w_ff  = (const float*)d_in[10];
    const float* b_ff  = (const float*)d_in[11];
    float* out = (float*)d_out;

    float *pooled, *nsrc;
    __nv_bfloat16 *h, *agg, *xs, *w, *win;
    cudaGetSymbolAddress((void**)&pooled, g_pooled);
    cudaGetSymbolAddress((void**)&nsrc,   g_norm_src);
    cudaGetSymbolAddress((void**)&h,      g_h);
    cudaGetSymbolAddress((void**)&agg,    g_agg);
    cudaGetSymbolAddress((void**)&xs,     g_xs);
    cudaGetSymbolAddress((void**)&w,      g_w);
    cudaGetSymbolAddress((void**)&win,    g_win);

    auto tg128 = tgemm_kernel<8, 528, 256, 512>;
    auto tg80  = tgemm_kernel<5, 336, 160, 320>;
    const int SM128 = 1024 + 3 * 128 * 528;   // 203,776
    const int SM80  = 1024 + 3 * 128 * 336;   // 130,048
    cudaFuncSetAttribute(tg128, cudaFuncAttributeMaxDynamicSharedMemorySize, SM128);
    cudaFuncSetAttribute(tg80,  cudaFuncAttributeMaxDynamicSharedMemorySize, SM80);

    // prep (1), degree (2), norm (3), tg80 (4) <- profiled launch
    prepx_kernel<<<(N_NODES * 32 + 255) / 256, 256>>>(gw, w_out, w_in, x);
    degree_kernel<<<(N_EDGES + 255) / 256, 256>>>(src, dst);
    norm_kernel<<<(N_NODES + 255) / 256, 256>>>();

    // h = silu(xs @ w_in + b_in) * norm_src   (persistent HMMA, K=80)
    tg80<<<NSM, 256, SM80>>>((const uint8_t*)xs, (const uint8_t*)win,
                             b_in, nsrc, h, nullptr);

    scan1_kernel<<<N_SCANB, SCAN_B>>>();
    scan2_kernel<<<1, 256>>>();
    scan3_kernel<<<(N_NODES + 255) / 256, 256>>>();
    build_csr_kernel<<<(N_EDGES + 255) / 256, 256>>>(src, dst);

    for (int l = 0; l < 3; l++) {
        gather_kernel<<<(N_NODES * 32 + 255) / 256, 256>>>();
        tg128<<<NSM, 256, SM128>>>((const uint8_t*)agg,
                                   (const uint8_t*)(w + (size_t)l * 128 * 256),
                                   gb + (size_t)l * HID, (l < 2) ? nsrc : nullptr,
                                   h, nullptr);
    }

    // pool: pooled[gid] += silu(h @ w_out + b_out)
    tg128<<<NSM, 256, SM128>>>((const uint8_t*)h,
                               (const uint8_t*)(w + (size_t)3 * 128 * 256),
                               b_out, nullptr, nullptr, gid);

    // out = pooled @ w_ff + b_ff  (fp32 FFMA)
    gemm_kernel<<<(N_GRAPHS + 127) / 128, 256>>>(pooled, N_GRAPHS, w_ff, b_ff, out);
}

// round 17
// speedup vs baseline: 1.1899x; 1.0329x over previous
#include <cuda_runtime.h>
#include <cuda_bf16.h>
#include <cstdint>

#define N_NODES  200000
#define N_EDGES  1600000
#define N_GRAPHS 10000
#define IN_F     74
#define HID      128

#define SCAN_B   1024
#define N_SCANB  ((N_NODES + SCAN_B - 1) / SCAN_B)   // 196
#define NSM      152
#define NTILES   ((N_NODES + 127) / 128)             // 1563

// interleaved split rows: h/agg = 256 bf16 [hi128|lo128] = 512B; x = 160 bf16 [hi80|lo80] = 320B
__device__ __align__(16) __nv_bfloat16 g_h  [(size_t)N_NODES * 256];
__device__ __align__(16) __nv_bfloat16 g_agg[(size_t)N_NODES * 256];
__device__ __align__(16) __nv_bfloat16 g_xs [(size_t)N_NODES * 160];
__device__ __align__(16) __nv_bfloat16 g_w  [4 * HID * 256];     // [l][n][hi128|lo128], W^T
__device__ __align__(16) __nv_bfloat16 g_win[HID * 160];         // w_in^T [n][hi80|lo80]
__device__ __align__(16) int   g_deg_out[N_NODES];
__device__ __align__(16) int   g_deg_in [N_NODES];
__device__ __align__(16) float g_norm_src[N_NODES];
__device__ __align__(16) float g_norm_dst[N_NODES];
__device__ __align__(16) float g_pooled[(size_t)N_GRAPHS * HID];
__device__ __align__(16) int   g_row_ptr[N_NODES + 1];
__device__ __align__(16) int   g_cursor [N_NODES];
__device__ __align__(16) int   g_csr_src[N_EDGES];
__device__ __align__(16) int   g_bsums  [N_SCANB];

__device__ __forceinline__ float fast_silu(float w) {
    float t, r;
    asm("ex2.approx.f32 %0, %1;" : "=f"(t) : "f"(-1.4426950408889634f * w));
    asm("rcp.approx.f32 %0, %1;" : "=f"(r) : "f"(1.f + t));
    return w * r;
}

__device__ __forceinline__ uint32_t smem_u32(const void* p) {
    uint32_t a;
    asm("{ .reg .u64 t; cvta.to.shared.u64 t, %1; cvt.u32.u64 %0, t; }" : "=r"(a) : "l"(p));
    return a;
}

__device__ __forceinline__ void mbar_wait(uint32_t mb, uint32_t parity) {
    asm volatile("{\n\t.reg .pred P1;\n\t"
                 "WL_%=:\n\t"
                 "mbarrier.try_wait.parity.acquire.cta.shared::cta.b64 P1, [%0], %1, 0x989680;\n\t"
                 "@P1 bra.uni WD_%=;\n\t"
                 "bra.uni WL_%=;\n\t"
                 "WD_%=:\n\t}" :: "r"(mb), "r"(parity) : "memory");
}

#define LDSM4(r, addr)                                                          \
    asm volatile("ldmatrix.sync.aligned.m8n8.x4.shared.b16 {%0,%1,%2,%3}, [%4];" \
                 : "=r"((r)[0]), "=r"((r)[1]), "=r"((r)[2]), "=r"((r)[3])        \
                 : "r"(addr))

#define MMA16816(c, a, b)                                                        \
    asm volatile("mma.sync.aligned.m16n8k16.row.col.f32.bf16.bf16.f32 "          \
                 "{%0,%1,%2,%3}, {%4,%5,%6,%7}, {%8,%9}, {%0,%1,%2,%3};"         \
                 : "+f"((c)[0]), "+f"((c)[1]), "+f"((c)[2]), "+f"((c)[3])        \
                 : "r"((a)[0]), "r"((a)[1]), "r"((a)[2]), "r"((a)[3]),           \
                   "r"((b)[0]), "r"((b)[1]))

__device__ __forceinline__ void split_store2(float va, float vb, __nv_bfloat16* hi_p,
                                             __nv_bfloat16* lo_p) {
    __nv_bfloat16 ha = __float2bfloat16(va);
    __nv_bfloat16 hb = __float2bfloat16(vb);
    *reinterpret_cast<uint32_t*>(hi_p) =
        (uint32_t)__bfloat16_as_ushort(ha) | ((uint32_t)__bfloat16_as_ushort(hb) << 16);
    *reinterpret_cast<uint32_t*>(lo_p) =
        (uint32_t)__bfloat16_as_ushort(__float2bfloat16(va - __bfloat162float(ha)))
      | ((uint32_t)__bfloat16_as_ushort(__float2bfloat16(vb - __bfloat162float(hb))) << 16);
}

// ---------------- fused prep: zeros + weight split/transpose + x split -----------------
__global__ __launch_bounds__(256) void prepx_kernel(const float* __restrict__ gw,
                                                    const float* __restrict__ w_out,
                                                    const float* __restrict__ w_in,
                                                    const float* __restrict__ x) {
    int i = blockIdx.x * blockDim.x + threadIdx.x;
    if (i < N_NODES / 4) {
        reinterpret_cast<int4*>(g_deg_out)[i] = make_int4(0, 0, 0, 0);
        reinterpret_cast<int4*>(g_deg_in )[i] = make_int4(0, 0, 0, 0);
    }
    if (i < N_GRAPHS * HID / 4)
        reinterpret_cast<float4*>(g_pooled)[i] = make_float4(0.f, 0.f, 0.f, 0.f);
    if (i < 4 * HID * HID) {
        int l = i >> 14, n = (i >> 7) & 127, k = i & 127;
        float v = (l < 3) ? gw[l * HID * HID + k * HID + n] : w_out[k * HID + n];
        __nv_bfloat16 hb = __float2bfloat16(v);
        size_t base = ((size_t)(l * 128 + n)) * 256;
        g_w[base + k]       = hb;
        g_w[base + 128 + k] = __float2bfloat16(v - __bfloat162float(hb));
    }
    if (i < HID * 80) {
        int n = i / 80, k = i % 80;
        float v = (k < IN_F) ? w_in[k * HID + n] : 0.f;
        __nv_bfloat16 hb = __float2bfloat16(v);
        g_win[n * 160 + k]      = hb;
        g_win[n * 160 + 80 + k] = __float2bfloat16(v - __bfloat162float(hb));
    }
    // x split: one warp per row
    int row  = i >> 5;
    int lane = i & 31;
    if (row < N_NODES) {
        const float* xr = x + (size_t)row * IN_F;
        __nv_bfloat16* o = g_xs + (size_t)row * 160;
#pragma unroll
        for (int c = lane; c < 80; c += 32) {
            float v = (c < IN_F) ? __ldg(xr + c) : 0.f;
            __nv_bfloat16 hb = __float2bfloat16(v);
            o[c]      = hb;
            o[80 + c] = __float2bfloat16(v - __bfloat162float(hb));
        }
    }
}

__global__ void degree_kernel(const int* __restrict__ src, const int* __restrict__ dst) {
    int i = blockIdx.x * blockDim.x + threadIdx.x;
    if (i < N_EDGES) {
        atomicAdd(&g_deg_out[src[i]], 1);
        atomicAdd(&g_deg_in [dst[i]], 1);
    }
}

__global__ void norm_kernel() {
    int i = blockIdx.x * blockDim.x + threadIdx.x;
    if (i < N_NODES) {
        g_norm_src[i] = rsqrtf(fmaxf((float)g_deg_out[i], 1.f));
        g_norm_dst[i] = rsqrtf(fmaxf((float)g_deg_in [i], 1.f));
    }
}

// ---------------- CSR build ----------------
__global__ __launch_bounds__(SCAN_B) void scan1_kernel() {
    __shared__ int sh[SCAN_B];
    int i = blockIdx.x * SCAN_B + threadIdx.x;
    int v = (i < N_NODES) ? g_deg_in[i] : 0;
    sh[threadIdx.x] = v;
    __syncthreads();
#pragma unroll
    for (int off = 1; off < SCAN_B; off <<= 1) {
        int t = (threadIdx.x >= off) ? sh[threadIdx.x - off] : 0;
        __syncthreads();
        sh[threadIdx.x] += t;
        __syncthreads();
    }
    if (i < N_NODES) g_row_ptr[i] = sh[threadIdx.x] - v;
    if (threadIdx.x == SCAN_B - 1) g_bsums[blockIdx.x] = sh[threadIdx.x];
}

__global__ __launch_bounds__(256) void scan2_kernel() {
    __shared__ int sh[256];
    int v = (threadIdx.x < N_SCANB) ? g_bsums[threadIdx.x] : 0;
    sh[threadIdx.x] = v;
    __syncthreads();
#pragma unroll
    for (int off = 1; off < 256; off <<= 1) {
        int t = (threadIdx.x >= off) ? sh[threadIdx.x - off] : 0;
        __syncthreads();
        sh[threadIdx.x] += t;
        __syncthreads();
    }
    if (threadIdx.x < N_SCANB) g_bsums[threadIdx.x] = sh[threadIdx.x] - v;
}

__global__ void scan3_kernel() {
    int i = blockIdx.x * blockDim.x + threadIdx.x;
    if (i < N_NODES) {
        int rp = g_row_ptr[i] + g_bsums[i / SCAN_B];
        g_row_ptr[i] = rp;
        g_cursor [i] = rp;
    }
    if (i == 0) g_row_ptr[N_NODES] = N_EDGES;
}

__global__ void build_csr_kernel(const int* __restrict__ src, const int* __restrict__ dst) {
    int e = blockIdx.x * blockDim.x + threadIdx.x;
    if (e < N_EDGES) {
        int pos = atomicAdd(&g_cursor[dst[e]], 1);
        g_csr_src[pos] = src[e];
    }
}

// ---------------- SpMM gather: one warp/node ----------------
__global__ __launch_bounds__(256) void gather_kernel() {
    int n    = (blockIdx.x * blockDim.x + threadIdx.x) >> 5;
    int lane = threadIdx.x & 31;
    if (n >= N_NODES) return;
    int e0 = __ldg(&g_row_ptr[n]);
    int e1 = __ldg(&g_row_ptr[n + 1]);
    float acc[8];
#pragma unroll
    for (int j = 0; j < 8; j++) acc[j] = 0.f;

    int e = e0;
    for (; e + 4 <= e1; e += 4) {
        int i0 = __ldg(&g_csr_src[e]);
        int i1 = __ldg(&g_csr_src[e + 1]);
        int i2 = __ldg(&g_csr_src[e + 2]);
        int i3 = __ldg(&g_csr_src[e + 3]);
        uint4 r0 = *reinterpret_cast<const uint4*>((const char*)g_h + (size_t)i0 * 512 + lane * 16);
        uint4 r1 = *reinterpret_cast<const uint4*>((const char*)g_h + (size_t)i1 * 512 + lane * 16);
        uint4 r2 = *reinterpret_cast<const uint4*>((const char*)g_h + (size_t)i2 * 512 + lane * 16);
        uint4 r3 = *reinterpret_cast<const uint4*>((const char*)g_h + (size_t)i3 * 512 + lane * 16);
        const uint32_t* p0 = &r0.x;
        const uint32_t* p1 = &r1.x;
        const uint32_t* p2 = &r2.x;
        const uint32_t* p3 = &r3.x;
#pragma unroll
        for (int q = 0; q < 4; q++) {
            __nv_bfloat162 u0 = *reinterpret_cast<const __nv_bfloat162*>(&p0[q]);
            __nv_bfloat162 u1 = *reinterpret_cast<const __nv_bfloat162*>(&p1[q]);
            __nv_bfloat162 u2 = *reinterpret_cast<const __nv_bfloat162*>(&p2[q]);
            __nv_bfloat162 u3 = *reinterpret_cast<const __nv_bfloat162*>(&p3[q]);
            acc[2 * q]     += (__bfloat162float(u0.x) + __bfloat162float(u1.x))
                            + (__bfloat162float(u2.x) + __bfloat162float(u3.x));
            acc[2 * q + 1] += (__bfloat162float(u0.y) + __bfloat162float(u1.y))
                            + (__bfloat162float(u2.y) + __bfloat162float(u3.y));
        }
    }
    for (; e < e1; e++) {
        int a = __ldg(&g_csr_src[e]);
        uint4 ra = *reinterpret_cast<const uint4*>((const char*)g_h + (size_t)a * 512 + lane * 16);
        const uint32_t* pa = &ra.x;
#pragma unroll
        for (int q = 0; q < 4; q++) {
            __nv_bfloat162 ua = *reinterpret_cast<const __nv_bfloat162*>(&pa[q]);
            acc[2 * q]     += __bfloat162float(ua.x);
            acc[2 * q + 1] += __bfloat162float(ua.y);
        }
    }
    float nd = __ldg(&g_norm_dst[n]);
    float w[8];
#pragma unroll
    for (int j = 0; j < 8; j++) {
        float other = __shfl_down_sync(0xffffffffu, acc[j], 16);
        w[j] = (acc[j] + other) * nd;
    }
    if (lane < 16) {
        __nv_bfloat16* rowp = g_agg + (size_t)n * 256;
#pragma unroll
        for (int q = 0; q < 4; q++)
            split_store2(w[2 * q], w[2 * q + 1],
                         rowp + lane * 8 + 2 * q,
                         rowp + 128 + lane * 8 + 2 * q);
    }
}

// ---------------- persistent HMMA GEMM: 512 threads (16 warps, 4/SMSP) -----------------
// W staged once (SMEM), A double-buffered. Warp tile 32x32: wm=wid>>2, wn=wid&3.
// smem: [0..48) 3 mbarriers (A0, A1, W), [64..576) bias, data from 1024.
template<int KSTEPS, int TROWB, int LOOFF, int ROWB>
__global__ __launch_bounds__(512)
void tgemm_kernel(const uint8_t* __restrict__ A8,
                  const uint8_t* __restrict__ W8,
                  const float* __restrict__ bias,
                  const float* __restrict__ out_scale,
                  __nv_bfloat16* __restrict__ o,
                  const int* __restrict__ gids)
{
    extern __shared__ char smem[];
    const int OFF_W  = 1024;
    const int OFF_A0 = OFF_W + 128 * TROWB;
    const int OFF_A1 = OFF_A0 + 128 * TROWB;
    uint32_t sb = smem_u32(smem);
    const int tid = threadIdx.x, wid = tid >> 5, lane = tid & 31;

    if (tid < 3)
        asm volatile("mbarrier.init.shared.b64 [%0], %1;"
                     :: "r"(sb + tid * 16), "r"(1u) : "memory");
    if (tid < 128) ((float*)(smem + 64))[tid] = bias[tid];
    __syncthreads();

    auto prefetch = [&](uint32_t mb, uint32_t dstOff, const uint8_t* src, int nrows) {
        asm volatile("mbarrier.arrive.expect_tx.shared.b64 _, [%0], %1;"
                     :: "r"(mb), "r"((uint32_t)(nrows * ROWB)) : "memory");
        for (int row = 0; row < nrows; row++)
            asm volatile("cp.async.bulk.shared::cluster.global.mbarrier::complete_tx::bytes "
                         "[%0], [%1], %2, [%3];"
                         :: "r"(sb + dstOff + row * TROWB), "l"(src + (size_t)row * ROWB),
                            "r"((uint32_t)ROWB), "r"(mb) : "memory");
    };

    int t0 = blockIdx.x;
    if (tid == 0) {
        prefetch(sb + 32, OFF_W, W8, 128);
        if (t0 < NTILES)
            prefetch(sb + 0, OFF_A0, A8 + (size_t)t0 * 128 * ROWB,
                     min(128, N_NODES - t0 * 128));
    }
    mbar_wait(sb + 32, 0);                    // W resident in SMEM for the whole kernel

    const int wm = wid >> 2, wn = wid & 3;    // 4x4 warp grid
    const int r0 = wm * 32, n0 = wn * 32;
    const int arow = lane & 15;
    const int akb  = (lane >> 4) << 4;
    const int bn   = (lane & 7) + ((lane >> 4) << 3);
    const int bkb  = ((lane >> 3) & 1) << 4;
    const float* bs = (const float*)(smem + 64);
    const int cp = n0 + (lane & 3) * 2;

    int cur = 0;
    uint32_t ph[2] = {0u, 0u};
    for (int t = t0; t < NTILES; t += NSM) {
        __syncthreads();   // all warps done reading buf cur^1 (previous tile)
        int nxt = t + NSM;
        if (nxt < NTILES && tid == 0)
            prefetch(sb + (cur ^ 1) * 16, (cur ? OFF_A0 : OFF_A1),
                     A8 + (size_t)nxt * 128 * ROWB, min(128, N_NODES - nxt * 128));

        mbar_wait(sb + cur * 16, ph[cur]);
        ph[cur] ^= 1;
        const int OFF_A = cur ? OFF_A1 : OFF_A0;
        const int row0 = t * 128;

        float acc[2][4][4];
#pragma unroll
        for (int m = 0; m < 2; m++)
#pragma unroll
            for (int j = 0; j < 4; j++)
#pragma unroll
                for (int q = 0; q < 4; q++) acc[m][j][q] = 0.f;

#pragma unroll
        for (int ks = 0; ks < KSTEPS; ks++) {
            uint32_t ah[2][4], al[2][4], bh[4][2], bl[4][2];
#pragma unroll
            for (int m = 0; m < 2; m++) {
                uint32_t ad = sb + OFF_A + (uint32_t)(r0 + m * 16 + arow) * TROWB + ks * 32 + akb;
                LDSM4(ah[m], ad);
                LDSM4(al[m], ad + LOOFF);
            }
#pragma unroll
            for (int jp = 0; jp < 2; jp++) {
                uint32_t bd = sb + OFF_W + (uint32_t)(n0 + jp * 16 + bn) * TROWB + ks * 32 + bkb;
                uint32_t r[4];
                LDSM4(r, bd);
                bh[2 * jp][0] = r[0]; bh[2 * jp][1] = r[1];
                bh[2 * jp + 1][0] = r[2]; bh[2 * jp + 1][1] = r[3];
                LDSM4(r, bd + LOOFF);
                bl[2 * jp][0] = r[0]; bl[2 * jp][1] = r[1];
                bl[2 * jp + 1][0] = r[2]; bl[2 * jp + 1][1] = r[3];
            }
#pragma unroll
            for (int m = 0; m < 2; m++)
#pragma unroll
                for (int j = 0; j < 4; j++) {
                    MMA16816(acc[m][j], ah[m], bh[j]);
                    MMA16816(acc[m][j], ah[m], bl[j]);
                    MMA16816(acc[m][j], al[m], bh[j]);
                }
        }

        // ---- epilogue (32 cols per warp) ----
        if (gids) {
            int curg = -1;
            float p[8];
#pragma unroll
            for (int m = 0; m < 2; m++) {
#pragma unroll
                for (int hf = 0; hf < 2; hf++) {
                    int gr = row0 + r0 + m * 16 + hf * 8 + (lane >> 2);
                    if (gr >= N_NODES) continue;
                    int g = __ldg(gids + gr);
                    float v[8];
#pragma unroll
                    for (int j = 0; j < 4; j++) {
                        int c = cp + j * 8;
                        v[2 * j]     = fast_silu(acc[m][j][hf * 2 + 0] + bs[c]);
                        v[2 * j + 1] = fast_silu(acc[m][j][hf * 2 + 1] + bs[c + 1]);
                    }
                    if (g == curg) {
#pragma unroll
                        for (int k = 0; k < 8; k++) p[k] += v[k];
                    } else {
                        if (curg >= 0) {
                            float* pb = g_pooled + (size_t)curg * 128 + cp;
#pragma unroll
                            for (int j = 0; j < 4; j++)
                                asm volatile("red.global.add.v2.f32 [%0], {%1,%2};"
                                             :: "l"(pb + j * 8), "f"(p[2 * j]), "f"(p[2 * j + 1])
                                             : "memory");
                        }
                        curg = g;
#pragma unroll
                        for (int k = 0; k < 8; k++) p[k] = v[k];
                    }
                }
            }
            if (curg >= 0) {
                float* pb = g_pooled + (size_t)curg * 128 + cp;
#pragma unroll
                for (int j = 0; j < 4; j++)
                    asm volatile("red.global.add.v2.f32 [%0], {%1,%2};"
                                 :: "l"(pb + j * 8), "f"(p[2 * j]), "f"(p[2 * j + 1])
                                 : "memory");
            }
        } else {
#pragma unroll
            for (int m = 0; m < 2; m++) {
#pragma unroll
                for (int hf = 0; hf < 2; hf++) {
                    int gr = row0 + r0 + m * 16 + hf * 8 + (lane >> 2);
                    if (gr >= N_NODES) continue;
                    float os = out_scale ? __ldg(out_scale + gr) : 1.f;
                    __nv_bfloat16* rowp = o + (size_t)gr * 256;
#pragma unroll
                    for (int j = 0; j < 4; j++) {
                        int c = cp + j * 8;
                        float va = fast_silu(acc[m][j][hf * 2 + 0] + bs[c]) * os;
                        float vb = fast_silu(acc[m][j][hf * 2 + 1] + bs[c + 1]) * os;
                        split_store2(va, vb, rowp + c, rowp + 128 + c);
                    }
                }
            }
        }
        cur ^= 1;
    }
    __syncthreads();
    if (tid < 3)
        asm volatile("mbarrier.inval.shared.b64 [%0];" :: "r"(sb + tid * 16) : "memory");
}

// ---------------- FFMA GEMM (final w_ff only) ----------------
__global__ __launch_bounds__(256, 2)
void gemm_kernel(const float* __restrict__ A, int M,
                 const float* __restrict__ B, const float* __restrict__ bias,
                 float* __restrict__ C)
{
    __shared__ unsigned long long As2[2][8][128];
    __shared__ float              Bs [2][8][128];

    const int t    = threadIdx.x;
    const int tx   = t & 15;
    const int ty   = t >> 4;
    const int row0 = blockIdx.x * 128;

    const int arow = t >> 1;
    const int akl  = (t & 1) * 4;
    const int brow = t >> 5;
    const int bcol = (t & 31) * 4;
    const int gr   = row0 + arow;

    unsigned long long acc[8][4];
#pragma unroll
    for (int i = 0; i < 8; i++)
#pragma unroll
        for (int j = 0; j < 4; j++) acc[i][j] = 0ULL;

    float4 aReg, bReg;
    auto load_regs = [&](int k0) {
        aReg = (gr < M) ? *reinterpret_cast<const float4*>(A + (size_t)gr * 128 + k0 + akl)
                        : make_float4(0.f, 0.f, 0.f, 0.f);
        bReg = *reinterpret_cast<const float4*>(B + (size_t)(k0 + brow) * 128 + bcol);
    };
    auto store_smem = [&](int buf) {
        unsigned long long p0, p1, p2, p3;
        asm("mov.b64 %0, {%1, %1};" : "=l"(p0) : "f"(aReg.x));
        asm("mov.b64 %0, {%1, %1};" : "=l"(p1) : "f"(aReg.y));
        asm("mov.b64 %0, {%1, %1};" : "=l"(p2) : "f"(aReg.z));
        asm("mov.b64 %0, {%1, %1};" : "=l"(p3) : "f"(aReg.w));
        As2[buf][akl + 0][arow] = p0;
        As2[buf][akl + 1][arow] = p1;
        As2[buf][akl + 2][arow] = p2;
        As2[buf][akl + 3][arow] = p3;
        *reinterpret_cast<float4*>(&Bs[buf][brow][bcol]) = bReg;
    };

    load_regs(0);
    store_smem(0);
    __syncthreads();
    int cur = 0;
    for (int c = 0; c < 16; c++) {
        const bool more = (c + 1 < 16);
        if (more) load_regs((c + 1) * 8);
#pragma unroll
        for (int k = 0; k < 8; k++) {
            ulonglong2 u0 = *reinterpret_cast<const ulonglong2*>(&Bs[cur][k][tx * 4]);
            ulonglong2 u1 = *reinterpret_cast<const ulonglong2*>(&Bs[cur][k][64 + tx * 4]);
            unsigned long long bp[4] = {u0.x, u0.y, u1.x, u1.y};
            const ulonglong2* ap = reinterpret_cast<const ulonglong2*>(&As2[cur][k][ty * 8]);
            ulonglong2 a01 = ap[0], a23 = ap[1], a45 = ap[2], a67 = ap[3];
            unsigned long long av[8] = {a01.x, a01.y, a23.x, a23.y,
                                        a45.x, a45.y, a67.x, a67.y};
#pragma unroll
            for (int i = 0; i < 8; i++)
#pragma unroll
                for (int j = 0; j < 4; j++)
                    asm("fma.rn.f32x2 %0, %1, %2, %0;"
                        : "+l"(acc[i][j]) : "l"(av[i]), "l"(bp[j]));
        }
        if (more) store_smem(cur ^ 1);
        __syncthreads();
        cur ^= 1;
    }

    float4 bb0 = *reinterpret_cast<const float4*>(bias + tx * 4);
    float4 bb1 = *reinterpret_cast<const float4*>(bias + 64 + tx * 4);
    float bia[8] = {bb0.x, bb0.y, bb0.z, bb0.w, bb1.x, bb1.y, bb1.z, bb1.w};
#pragma unroll
    for (int i = 0; i < 8; i++) {
        int r = row0 + ty * 8 + i;
        if (r >= M) break;
        float v[8];
#pragma unroll
        for (int j = 0; j < 4; j++) {
            float lo, hi;
            asm("mov.b64 {%0, %1}, %2;" : "=f"(lo), "=f"(hi) : "l"(acc[i][j]));
            v[2 * j] = lo + bia[2 * j];
            v[2 * j + 1] = hi + bia[2 * j + 1];
        }
        *reinterpret_cast<float4*>(C + (size_t)r * 128 + tx * 4) =
            make_float4(v[0], v[1], v[2], v[3]);
        *reinterpret_cast<float4*>(C + (size_t)r * 128 + 64 + tx * 4) =
            make_float4(v[4], v[5], v[6], v[7]);
    }
}

// ---------------- launch ----------------
extern "C" void kernel_launch(void* const* d_in, const int* in_sizes, int n_in,
                              void* d_out, int out_size) {
    const float* x     = (const float*)d_in[0];
    const int*   src   = (const int*)  d_in[1];
    const int*   dst   = (const int*)  d_in[2];
    const int*   gid   = (const int*)  d_in[3];
    const float* w_in  = (const float*)d_in[4];
    const float* b_in  = (const float*)d_in[5];
    const float* gw    = (const float*)d_in[6];
    const float* gb    = (const float*)d_in[7];
    const float* w_out = (const float*)d_in[8];
    const float* b_out = (const float*)d_in[9];
    const float* w_ff  = (const float*)d_in[10];
    const float* b_ff  = (const float*)d_in[11];
    float* out = (float*)d_out;

    float *pooled, *nsrc;
    __nv_bfloat16 *h, *agg, *xs, *w, *win;
    cudaGetSymbolAddress((void**)&pooled, g_pooled);
    cudaGetSymbolAddress((void**)&nsrc,   g_norm_src);
    cudaGetSymbolAddress((void**)&h,      g_h);
    cudaGetSymbolAddress((void**)&agg,    g_agg);
    cudaGetSymbolAddress((void**)&xs,     g_xs);
    cudaGetSymbolAddress((void**)&w,      g_w);
    cudaGetSymbolAddress((void**)&win,    g_win);

    auto tg128 = tgemm_kernel<8, 528, 256, 512>;
    auto tg80  = tgemm_kernel<5, 336, 160, 320>;
    const int SM128 = 1024 + 3 * 128 * 528;   // 203,776
    const int SM80  = 1024 + 3 * 128 * 336;   // 130,048
    cudaFuncSetAttribute(tg128, cudaFuncAttributeMaxDynamicSharedMemorySize, SM128);
    cudaFuncSetAttribute(tg80,  cudaFuncAttributeMaxDynamicSharedMemorySize, SM80);

    // prep (1), degree (2), norm (3), tg80 (4) <- profiled launch
    prepx_kernel<<<(N_NODES * 32 + 255) / 256, 256>>>(gw, w_out, w_in, x);
    degree_kernel<<<(N_EDGES + 255) / 256, 256>>>(src, dst);
    norm_kernel<<<(N_NODES + 255) / 256, 256>>>();

    // h = silu(xs @ w_in + b_in) * norm_src   (persistent HMMA, K=80, 512 thr)
    tg80<<<NSM, 512, SM80>>>((const uint8_t*)xs, (const uint8_t*)win,
                             b_in, nsrc, h, nullptr);

    scan1_kernel<<<N_SCANB, SCAN_B>>>();
    scan2_kernel<<<1, 256>>>();
    scan3_kernel<<<(N_NODES + 255) / 256, 256>>>();
    build_csr_kernel<<<(N_EDGES + 255) / 256, 256>>>(src, dst);

    for (int l = 0; l < 3; l++) {
        gather_kernel<<<(N_NODES * 32 + 255) / 256, 256>>>();
        tg128<<<NSM, 512, SM128>>>((const uint8_t*)agg,
                                   (const uint8_t*)(w + (size_t)l * 128 * 256),
                                   gb + (size_t)l * HID, (l < 2) ? nsrc : nullptr,
                                   h, nullptr);
    }

    // pool: pooled[gid] += silu(h @ w_out + b_out)
    tg128<<<NSM, 512, SM128>>>((const uint8_t*)h,
                               (const uint8_t*)(w + (size_t)3 * 128 * 256),
                               b_out, nullptr, nullptr, gid);

    // out = pooled @ w_ff + b_ff  (fp32 FFMA)
    gemm_kernel<<<(N_GRAPHS + 127) / 128, 256>>>(pooled, N_GRAPHS, w_ff, b_ff, out);
}